// round 11
// baseline (speedup 1.0000x reference)
#include <cuda_runtime.h>
#include <cuda_fp16.h>

#define N_POINTS 1000000
#define GRID_D   128
#define CH       32
#define CHP      16                            // channels per pass
#define NVOX     (GRID_D * GRID_D * GRID_D)    // 2,097,152

// Two 64MB fp16 half-grids, voxel-major: [pass][vox][16ch].
__device__ __half g_feat_h[2 * (size_t)NVOX * CHP];

// ---------------------------------------------------------------------------
// Transpose one 16-channel half: (16ch, V) fp32 -> (V, 16ch) fp16.
// (unchanged — measured at memory roofline)
// ---------------------------------------------------------------------------
__global__ __launch_bounds__(256) void transpose_half(const float* __restrict__ feature,
                                                      int pass) {
    __shared__ float tile[CHP * 256];
    const int t  = threadIdx.x;
    const int s0 = blockIdx.x * 256;
    const int ch_base = pass * CHP;
    __half* dst = g_feat_h + (size_t)pass * NVOX * CHP;

    float4 v[4];
    #pragma unroll
    for (int r = 0; r < 4; ++r) {
        const int i  = r * 256 + t;
        const int ch = i >> 6;
        const int c4 = i & 63;
        v[r] = __ldcs(reinterpret_cast<const float4*>(
                  &feature[(size_t)(ch_base + ch) * NVOX + s0 + c4 * 4]));
    }
    #pragma unroll
    for (int r = 0; r < 4; ++r) {
        const int i   = r * 256 + t;
        const int ch  = i >> 6;
        const int c4  = i & 63;
        const int col = (c4 * 4) ^ (((ch >> 3) & 1) * 16);
        *reinterpret_cast<float4*>(&tile[ch * 256 + col]) = v[r];
    }
    __syncthreads();

    #pragma unroll
    for (int r = 0; r < 2; ++r) {
        const int i   = r * 256 + t;
        const int vox = i >> 1;
        const int oct = i & 1;
        half2 h[4];
        #pragma unroll
        for (int kk = 0; kk < 4; ++kk) {
            const int ch0 = oct * 8 + kk * 2;
            const int ch1 = ch0 + 1;
            const int s   = ((ch0 >> 3) & 1) * 16;
            const float a = tile[ch0 * 256 + (vox ^ s)];
            const float b = tile[ch1 * 256 + (vox ^ s)];
            h[kk] = __floats2half2_rn(a, b);
        }
        uint4 o;
        o.x = *reinterpret_cast<unsigned*>(&h[0]);
        o.y = *reinterpret_cast<unsigned*>(&h[1]);
        o.z = *reinterpret_cast<unsigned*>(&h[2]);
        o.w = *reinterpret_cast<unsigned*>(&h[3]);
        *reinterpret_cast<uint4*>(&dst[(size_t)(s0 + vox) * CHP + oct * 8]) = o;
    }
}

// ---------------------------------------------------------------------------
// Gather one 16-channel half. 4 lanes/point: q = (xs<<1)|oc.
// Clamp-free addressing: OOB corners have weight 0, so the index only needs
// to be IN-BOUNDS -> mask coords with &127 and bit-pack a 32-bit byte offset
//   off = (zi&127)<<19 | (yi&127)<<12 | (xi&127)<<5     (oc*16 in base ptr)
// No 64-bit IMAD chains, no min/max clamps.
// ---------------------------------------------------------------------------
__global__ __launch_bounds__(256) void gather_half(const float* __restrict__ x,
                                                   float* __restrict__ out,
                                                   int pass) {
    const int tid = blockIdx.x * blockDim.x + threadIdx.x;
    const int p   = tid >> 2;                  // point index (grid divides exactly)
    const int q   = tid & 3;
    const int oc  = q & 1;                     // channel octet (8 ch)
    const int xs  = q >> 1;                    // x-corner owned by this lane
    const char* gbase = reinterpret_cast<const char*>(
        g_feat_h + (size_t)pass * NVOX * CHP) + (oc << 4);

    const float px = __ldg(&x[3 * p + 0]);
    const float py = __ldg(&x[3 * p + 1]);
    const float pz = __ldg(&x[3 * p + 2]);

    // fx = x*6.4 + 63.5  (LO=-10, HI=10, W=128)
    const float fx = fmaf(px, 6.4f, 63.5f);
    const float fy = fmaf(py, 6.4f, 63.5f);
    const float fz = fmaf(pz, 6.4f, 63.5f);

    const int x0 = __float2int_rd(fx);
    const int y0 = __float2int_rd(fy);
    const int z0 = __float2int_rd(fz);
    const float wx = fx - (float)x0;
    const float wy = fy - (float)y0;
    const float wz = fz - (float)z0;

    // this lane's x corner; validity folded into the weight
    const int      xi  = x0 + xs;
    const float    wxt = (xs ? wx : 1.0f - wx) *
                         (((unsigned)xi < (unsigned)GRID_D) ? 1.0f : 0.0f);
    const unsigned xoff = (unsigned)(xi & 127) << 5;

    float    w4[4];
    unsigned off[4];
    #pragma unroll
    for (int c = 0; c < 4; ++c) {
        const int dy = c & 1, dz = c >> 1;
        const int yi = y0 + dy, zi = z0 + dz;
        const bool v = ((unsigned)yi < (unsigned)GRID_D) &&
                       ((unsigned)zi < (unsigned)GRID_D);
        const float wyt = dy ? wy : 1.0f - wy;
        const float wzt = dz ? wz : 1.0f - wz;
        w4[c]  = v ? (wxt * wyt * wzt) : 0.0f;
        off[c] = ((unsigned)(zi & 127) << 19) | ((unsigned)(yi & 127) << 12) | xoff;
    }

    uint4 cv[4];
    #pragma unroll
    for (int c = 0; c < 4; ++c)
        cv[c] = *reinterpret_cast<const uint4*>(gbase + off[c]);

    float acc[8] = {0.f, 0.f, 0.f, 0.f, 0.f, 0.f, 0.f, 0.f};
    #pragma unroll
    for (int c = 0; c < 4; ++c) {
        const unsigned u[4] = {cv[c].x, cv[c].y, cv[c].z, cv[c].w};
        #pragma unroll
        for (int kk = 0; kk < 4; ++kk) {
            const half2  h2 = *reinterpret_cast<const half2*>(&u[kk]);
            const float2 f2 = __half22float2(h2);
            acc[kk * 2 + 0] = fmaf(w4[c], f2.x, acc[kk * 2 + 0]);
            acc[kk * 2 + 1] = fmaf(w4[c], f2.y, acc[kk * 2 + 1]);
        }
    }

    // combine dx=0 and dx=1 partial sums (lanes differ in bit 1 of q)
    #pragma unroll
    for (int k = 0; k < 8; ++k)
        acc[k] += __shfl_xor_sync(0xffffffff, acc[k], 2);

    const float4 st = xs ? make_float4(acc[4], acc[5], acc[6], acc[7])
                         : make_float4(acc[0], acc[1], acc[2], acc[3]);
    float* op = out + (size_t)p * CH + pass * CHP + oc * 8 + xs * 4;
    __stcs(reinterpret_cast<float4*>(op), st);
}

extern "C" void kernel_launch(void* const* d_in, const int* in_sizes, int n_in,
                              void* d_out, int out_size) {
    const float* x       = (const float*)d_in[0];   // (N_POINTS, 3)
    const float* feature = (const float*)d_in[1];   // (32, 128, 128, 128)
    float*       out     = (float*)d_out;           // (N_POINTS, 32)

    const int tblocks = NVOX / 256;
    const int gblocks = (N_POINTS * 4) / 256;        // exact

    transpose_half<<<tblocks, 256>>>(feature, 0);
    gather_half<<<gblocks, 256>>>(x, out, 0);

    transpose_half<<<tblocks, 256>>>(feature, 1);
    gather_half<<<gblocks, 256>>>(x, out, 1);
}